// round 2
// baseline (speedup 1.0000x reference)
#include <cuda_runtime.h>

// Problem constants
#define BATCH   4
#define CDIM    256
#define NTOK    2304        // 48*48
#define NH      8
#define HD      64
#define HIDDEN  (NH*HD)     // 512
#define NEG_INF (-3.0e38f)

// Scratch (head-major): [B, h, N, 64]
__device__ __align__(16) float g_Q[(size_t)BATCH*NH*NTOK*HD];
__device__ __align__(16) float g_K[(size_t)BATCH*NH*NTOK*HD];
__device__ __align__(16) float g_V[(size_t)BATCH*NH*NTOK*HD];
__device__ __align__(16) float g_O[(size_t)BATCH*NH*NTOK*HD];

// ---------------------------------------------------------------------------
// Kernel 1: QKV projection.
// t[b,n,c] = x[b,c,n]; out[b,h,n,d] = sum_c t[b,n,c] * W[c, h*64+d]
// Grid: (NTOK/64, 3*HIDDEN/64, BATCH). Block 256 (16x16), 4x4 micro-tile.
// ---------------------------------------------------------------------------
__global__ __launch_bounds__(256) void qkv_proj_kernel(
    const float* __restrict__ x,
    const float* __restrict__ Wq,
    const float* __restrict__ Wk,
    const float* __restrict__ Wv)
{
    __shared__ float As[16][64];   // [k][m]  (m contiguous in x)
    __shared__ float Bs[16][64];   // [k][n]

    const int b    = blockIdx.z;
    const int m0   = blockIdx.x * 64;
    const int sel  = blockIdx.y >> 3;          // 0=q, 1=k, 2=v
    const int h    = blockIdx.y & 7;
    const int nc0  = h * 64;

    const float* __restrict__ W  = (sel == 0) ? Wq : (sel == 1) ? Wk : Wv;
    float* __restrict__ Out      = (sel == 0) ? g_Q : (sel == 1) ? g_K : g_V;

    const int tid = threadIdx.x;
    const int tx  = tid & 15;
    const int ty  = tid >> 4;
    const int lk  = tid >> 4;          // 0..15
    const int lm  = (tid & 15) * 4;    // 0..60

    const float* __restrict__ xb = x + (size_t)b * CDIM * NTOK;

    float acc[4][4] = {};

    for (int k0 = 0; k0 < CDIM; k0 += 16) {
        float4 av = *(const float4*)(xb + (size_t)(k0 + lk) * NTOK + m0 + lm);
        float4 bv = *(const float4*)(W  + (size_t)(k0 + lk) * HIDDEN + nc0 + lm);
        *(float4*)&As[lk][lm] = av;
        *(float4*)&Bs[lk][lm] = bv;
        __syncthreads();
        #pragma unroll
        for (int kk = 0; kk < 16; kk++) {
            float4 a  = *(float4*)&As[kk][ty * 4];
            float4 bb = *(float4*)&Bs[kk][tx * 4];
            float ar[4] = {a.x, a.y, a.z, a.w};
            float br[4] = {bb.x, bb.y, bb.z, bb.w};
            #pragma unroll
            for (int i = 0; i < 4; i++)
                #pragma unroll
                for (int j = 0; j < 4; j++)
                    acc[i][j] = fmaf(ar[i], br[j], acc[i][j]);
        }
        __syncthreads();
    }

    float* __restrict__ o = Out + ((size_t)(b * NH + h) * NTOK + m0) * HD;
    #pragma unroll
    for (int i = 0; i < 4; i++) {
        float4 v = make_float4(acc[i][0], acc[i][1], acc[i][2], acc[i][3]);
        *(float4*)(o + (size_t)(ty * 4 + i) * HD + tx * 4) = v;
    }
}

// ---------------------------------------------------------------------------
// Kernel 2: flash attention per (b,h).  64-row Q tile, 64-row KV tiles.
// attn = softmax(QK^T)/8 ;  o = attn @ V  (softmax-then-scale quirk folded
// into final normalization: rows of softmax sum to 1).
// Grid: (NTOK/64, BATCH*NH). Block 256 (16x16), 4x4 micro-tiles.
// ---------------------------------------------------------------------------
__global__ __launch_bounds__(256) void flash_attn_kernel()
{
    __shared__ float Qs[64][64];   // [d][m]   (transposed once)
    __shared__ float Ks[64][64];   // [d][j] during S; reused as P [j][m]
    __shared__ float Vs[64][64];   // [j][d]

    const int bh  = blockIdx.y;
    const int q0  = blockIdx.x * 64;
    const int tid = threadIdx.x;
    const int tx  = tid & 15;
    const int ty  = tid >> 4;

    const float* __restrict__ Qg = g_Q + (size_t)bh * NTOK * HD;
    const float* __restrict__ Kg = g_K + (size_t)bh * NTOK * HD;
    const float* __restrict__ Vg = g_V + (size_t)bh * NTOK * HD;

    // Load Q tile transposed: Qs[d][m] = Q[q0+m][d]
    for (int idx = tid; idx < 64 * 64; idx += 256) {
        int d = idx & 63;
        int m = idx >> 6;
        Qs[d][m] = Qg[(size_t)(q0 + m) * HD + d];
    }

    float o[4][4] = {};
    float mI[4], lI[4];
    #pragma unroll
    for (int i = 0; i < 4; i++) { mI[i] = NEG_INF; lI[i] = 0.0f; }

    const int lj  = tid >> 4;          // 0..15
    const int ld4 = (tid & 15) * 4;    // 0..60

    __syncthreads();

    for (int kv0 = 0; kv0 < NTOK; kv0 += 64) {
        // Load K transposed to [d][j]; V natural [j][d]
        #pragma unroll
        for (int r = 0; r < 4; r++) {
            int j = lj + r * 16;
            float4 kv = *(const float4*)(Kg + (size_t)(kv0 + j) * HD + ld4);
            Ks[ld4 + 0][j] = kv.x;
            Ks[ld4 + 1][j] = kv.y;
            Ks[ld4 + 2][j] = kv.z;
            Ks[ld4 + 3][j] = kv.w;
            float4 vv = *(const float4*)(Vg + (size_t)(kv0 + j) * HD + ld4);
            *(float4*)&Vs[j][ld4] = vv;
        }
        __syncthreads();

        // S = Q @ K^T  (64x64x64)
        float s[4][4] = {};
        #pragma unroll 8
        for (int kk = 0; kk < 64; kk++) {
            float4 a  = *(float4*)&Qs[kk][ty * 4];
            float4 bb = *(float4*)&Ks[kk][tx * 4];
            float ar[4] = {a.x, a.y, a.z, a.w};
            float br[4] = {bb.x, bb.y, bb.z, bb.w};
            #pragma unroll
            for (int i = 0; i < 4; i++)
                #pragma unroll
                for (int j = 0; j < 4; j++)
                    s[i][j] = fmaf(ar[i], br[j], s[i][j]);
        }

        // Online softmax (row groups of 16 lanes share a ty; width-16 shfl)
        #pragma unroll
        for (int i = 0; i < 4; i++) {
            float mx = fmaxf(fmaxf(s[i][0], s[i][1]), fmaxf(s[i][2], s[i][3]));
            #pragma unroll
            for (int w = 8; w >= 1; w >>= 1)
                mx = fmaxf(mx, __shfl_xor_sync(0xffffffffu, mx, w, 16));
            float mnew  = fmaxf(mI[i], mx);
            float alpha = __expf(mI[i] - mnew);
            float rs = 0.0f;
            #pragma unroll
            for (int j = 0; j < 4; j++) {
                s[i][j] = __expf(s[i][j] - mnew);
                rs += s[i][j];
            }
            #pragma unroll
            for (int w = 8; w >= 1; w >>= 1)
                rs += __shfl_xor_sync(0xffffffffu, rs, w, 16);
            lI[i] = lI[i] * alpha + rs;
            mI[i] = mnew;
            #pragma unroll
            for (int j = 0; j < 4; j++) o[i][j] *= alpha;
        }
        __syncthreads();   // everyone done reading Ks as K

        // Stage P transposed: Ks (as P) [j][m] = p[m][j]
        #pragma unroll
        for (int i = 0; i < 4; i++)
            #pragma unroll
            for (int j = 0; j < 4; j++)
                Ks[tx * 4 + j][ty * 4 + i] = s[i][j];
        __syncthreads();

        // O += P @ V  (64x64x64)
        #pragma unroll 8
        for (int kk = 0; kk < 64; kk++) {
            float4 a  = *(float4*)&Ks[kk][ty * 4];   // P[m][kk]
            float4 bb = *(float4*)&Vs[kk][tx * 4];   // V[kk][d]
            float ar[4] = {a.x, a.y, a.z, a.w};
            float br[4] = {bb.x, bb.y, bb.z, bb.w};
            #pragma unroll
            for (int i = 0; i < 4; i++)
                #pragma unroll
                for (int j = 0; j < 4; j++)
                    o[i][j] = fmaf(ar[i], br[j], o[i][j]);
        }
        __syncthreads();   // before next iter overwrites Ks/Vs
    }

    // Normalize: softmax row-sum and the post-softmax 1/sqrt(dk)=1/8 scale
    float* __restrict__ Og = g_O + (size_t)bh * NTOK * HD;
    #pragma unroll
    for (int i = 0; i < 4; i++) {
        float inv = 1.0f / (lI[i] * 8.0f);
        float4 v = make_float4(o[i][0] * inv, o[i][1] * inv,
                               o[i][2] * inv, o[i][3] * inv);
        *(float4*)(Og + (size_t)(q0 + ty * 4 + i) * HD + tx * 4) = v;
    }
}

// ---------------------------------------------------------------------------
// Kernel 3: output projection + transpose back to [B, C, H, W].
// out[b,c,n] = sum_j O[b,n,j] * Wo[j,c],  O head-major in g_O.
// Grid: (NTOK/64, CDIM/64, BATCH). Block 256, 4x4 micro-tile, smem-staged
// transposed write for coalescing.
// ---------------------------------------------------------------------------
__global__ __launch_bounds__(256) void out_proj_kernel(
    const float* __restrict__ Wo,
    float* __restrict__ out)
{
    __shared__ float As[16][64];   // [k][m]
    __shared__ float Bs[16][64];   // [k][c]
    __shared__ float Cs[64][64];   // [c][m]

    const int b   = blockIdx.z;
    const int m0  = blockIdx.x * 64;
    const int c0  = blockIdx.y * 64;
    const int tid = threadIdx.x;
    const int tx  = tid & 15;
    const int ty  = tid >> 4;

    const int am  = tid >> 2;         // 0..63
    const int ak4 = (tid & 3) * 4;    // 0,4,8,12
    const int bk  = tid >> 4;         // 0..15
    const int bc4 = (tid & 15) * 4;   // 0..60

    float acc[4][4] = {};

    for (int k0 = 0; k0 < HIDDEN; k0 += 16) {
        const int head = k0 >> 6;               // 16 | 64 so tile stays in one head
        const int kin  = (k0 & 63) + ak4;
        float4 av = *(const float4*)(g_O +
            ((size_t)(b * NH + head) * NTOK + m0 + am) * HD + kin);
        As[ak4 + 0][am] = av.x;
        As[ak4 + 1][am] = av.y;
        As[ak4 + 2][am] = av.z;
        As[ak4 + 3][am] = av.w;
        float4 bv = *(const float4*)(Wo + (size_t)(k0 + bk) * CDIM + c0 + bc4);
        *(float4*)&Bs[bk][bc4] = bv;
        __syncthreads();
        #pragma unroll
        for (int kk = 0; kk < 16; kk++) {
            float4 a  = *(float4*)&As[kk][ty * 4];
            float4 bb = *(float4*)&Bs[kk][tx * 4];
            float ar[4] = {a.x, a.y, a.z, a.w};
            float br[4] = {bb.x, bb.y, bb.z, bb.w};
            #pragma unroll
            for (int i = 0; i < 4; i++)
                #pragma unroll
                for (int j = 0; j < 4; j++)
                    acc[i][j] = fmaf(ar[i], br[j], acc[i][j]);
        }
        __syncthreads();
    }

    // Stage transposed: Cs[c][m]
    #pragma unroll
    for (int i = 0; i < 4; i++)
        #pragma unroll
        for (int j = 0; j < 4; j++)
            Cs[tx * 4 + j][ty * 4 + i] = acc[i][j];
    __syncthreads();

    // Coalesced write along n
    float* __restrict__ ob = out + ((size_t)b * CDIM + c0) * NTOK + m0;
    #pragma unroll
    for (int r = 0; r < 4; r++) {
        int idx = tid + r * 256;          // 0..1023 (64 c-rows * 16 float4s)
        int c   = idx >> 4;
        int m4  = (idx & 15) * 4;
        *(float4*)(ob + (size_t)c * NTOK + m4) = *(float4*)&Cs[c][m4];
    }
}

// ---------------------------------------------------------------------------
extern "C" void kernel_launch(void* const* d_in, const int* in_sizes, int n_in,
                              void* d_out, int out_size)
{
    const float* x  = (const float*)d_in[0];
    const float* Wq = (const float*)d_in[1];
    const float* Wk = (const float*)d_in[2];
    const float* Wv = (const float*)d_in[3];
    const float* Wo = (const float*)d_in[4];
    float* out = (float*)d_out;

    dim3 g1(NTOK / 64, 3 * HIDDEN / 64, BATCH);   // 36 x 24 x 4
    qkv_proj_kernel<<<g1, 256>>>(x, Wq, Wk, Wv);

    dim3 g2(NTOK / 64, BATCH * NH);               // 36 x 32
    flash_attn_kernel<<<g2, 256>>>();

    dim3 g3(NTOK / 64, CDIM / 64, BATCH);         // 36 x 4 x 4
    out_proj_kernel<<<g3, 256>>>(Wo, out);
}

// round 3
// speedup vs baseline: 3.0472x; 3.0472x over previous
#include <cuda_runtime.h>
#include <cstdint>

// Problem constants
#define BATCH   4
#define CDIM    256
#define NTOK    2304        // 48*48
#define NH      8
#define HD      64
#define HIDDEN  (NH*HD)     // 512
#define NEG_INF (-3.0e38f)

// Scratch (head-major): [B, h, N, 64]
__device__ __align__(16) float g_Q[(size_t)BATCH*NH*NTOK*HD];
__device__ __align__(16) float g_K[(size_t)BATCH*NH*NTOK*HD];
__device__ __align__(16) float g_V[(size_t)BATCH*NH*NTOK*HD];
__device__ __align__(16) float g_O[(size_t)BATCH*NH*NTOK*HD];

// ---------------------------------------------------------------------------
// tf32 helpers
// ---------------------------------------------------------------------------
__device__ __forceinline__ uint32_t f2tf32(float x) {
    uint32_t u;
    asm("cvt.rna.tf32.f32 %0, %1;" : "=r"(u) : "f"(x));
    return u;
}

__device__ __forceinline__ void mma_tf32(float c[4], const uint32_t a[4],
                                         uint32_t b0, uint32_t b1) {
    asm volatile(
        "mma.sync.aligned.m16n8k8.row.col.f32.tf32.tf32.f32 "
        "{%0,%1,%2,%3}, {%4,%5,%6,%7}, {%8,%9}, {%0,%1,%2,%3};"
        : "+f"(c[0]), "+f"(c[1]), "+f"(c[2]), "+f"(c[3])
        : "r"(a[0]), "r"(a[1]), "r"(a[2]), "r"(a[3]), "r"(b0), "r"(b1));
}

// ---------------------------------------------------------------------------
// Kernel 1: QKV projection (unchanged fp32 FFMA this round).
// ---------------------------------------------------------------------------
__global__ __launch_bounds__(256) void qkv_proj_kernel(
    const float* __restrict__ x,
    const float* __restrict__ Wq,
    const float* __restrict__ Wk,
    const float* __restrict__ Wv)
{
    __shared__ float As[16][64];
    __shared__ float Bs[16][64];

    const int b    = blockIdx.z;
    const int m0   = blockIdx.x * 64;
    const int sel  = blockIdx.y >> 3;
    const int h    = blockIdx.y & 7;
    const int nc0  = h * 64;

    const float* __restrict__ W  = (sel == 0) ? Wq : (sel == 1) ? Wk : Wv;
    float* __restrict__ Out      = (sel == 0) ? g_Q : (sel == 1) ? g_K : g_V;

    const int tid = threadIdx.x;
    const int tx  = tid & 15;
    const int ty  = tid >> 4;
    const int lk  = tid >> 4;
    const int lm  = (tid & 15) * 4;

    const float* __restrict__ xb = x + (size_t)b * CDIM * NTOK;

    float acc[4][4] = {};

    for (int k0 = 0; k0 < CDIM; k0 += 16) {
        float4 av = *(const float4*)(xb + (size_t)(k0 + lk) * NTOK + m0 + lm);
        float4 bv = *(const float4*)(W  + (size_t)(k0 + lk) * HIDDEN + nc0 + lm);
        *(float4*)&As[lk][lm] = av;
        *(float4*)&Bs[lk][lm] = bv;
        __syncthreads();
        #pragma unroll
        for (int kk = 0; kk < 16; kk++) {
            float4 a  = *(float4*)&As[kk][ty * 4];
            float4 bb = *(float4*)&Bs[kk][tx * 4];
            float ar[4] = {a.x, a.y, a.z, a.w};
            float br[4] = {bb.x, bb.y, bb.z, bb.w};
            #pragma unroll
            for (int i = 0; i < 4; i++)
                #pragma unroll
                for (int j = 0; j < 4; j++)
                    acc[i][j] = fmaf(ar[i], br[j], acc[i][j]);
        }
        __syncthreads();
    }

    float* __restrict__ o = Out + ((size_t)(b * NH + h) * NTOK + m0) * HD;
    #pragma unroll
    for (int i = 0; i < 4; i++) {
        float4 v = make_float4(acc[i][0], acc[i][1], acc[i][2], acc[i][3]);
        *(float4*)(o + (size_t)(ty * 4 + i) * HD + tx * 4) = v;
    }
}

// ---------------------------------------------------------------------------
// Kernel 2: flash attention on tensor cores (tf32 mma.sync m16n8k8).
// Block = 128 threads (4 warps); each warp owns 16 Q rows of a 64-row tile.
// KV tiles of 64 rows staged in smem (tf32-converted at staging).
//   Ks: [j][d] stride 68  -> S-phase B-frag reads conflict-free (bank=4j+d)
//   Vs: [j][d] stride 72  -> PV-phase B-frag reads conflict-free (bank=8j+d)
// P (post-softmax, tf32) reuses Ks storage; each warp's 16 rows are private.
// Grid: (NTOK/64, BATCH*NH).
// ---------------------------------------------------------------------------
#define KS_STRIDE 68
#define VS_STRIDE 72

__global__ __launch_bounds__(128, 3) void flash_attn_tc_kernel()
{
    __shared__ uint32_t Ks[64 * KS_STRIDE];  // K (tf32); reused as P after S
    __shared__ uint32_t Vs[64 * VS_STRIDE];  // V (tf32)

    const int bh   = blockIdx.y;
    const int q0   = blockIdx.x * 64;
    const int tid  = threadIdx.x;
    const int lane = tid & 31;
    const int warp = tid >> 5;
    const int g    = lane >> 2;     // groupID (0..7)
    const int t4   = lane & 3;      // threadID-in-group

    const float* __restrict__ Qg = g_Q + (size_t)bh * NTOK * HD;
    const float* __restrict__ Kg = g_K + (size_t)bh * NTOK * HD;
    const float* __restrict__ Vg = g_V + (size_t)bh * NTOK * HD;

    // Q A-fragments for all 8 k-steps, held in registers for the whole kernel
    uint32_t qa[8][4];
    {
        const float* q_r0 = Qg + (size_t)(q0 + warp * 16 + g) * HD;
        const float* q_r1 = q_r0 + 8 * HD;
        #pragma unroll
        for (int ks = 0; ks < 8; ks++) {
            qa[ks][0] = f2tf32(q_r0[ks * 8 + t4]);
            qa[ks][1] = f2tf32(q_r1[ks * 8 + t4]);
            qa[ks][2] = f2tf32(q_r0[ks * 8 + t4 + 4]);
            qa[ks][3] = f2tf32(q_r1[ks * 8 + t4 + 4]);
        }
    }

    float oc[8][4] = {};                       // O accumulators (8 n-tiles)
    float mrow[2] = {NEG_INF, NEG_INF};        // online-softmax state
    float lrow[2] = {0.0f, 0.0f};

    const int srow = tid >> 4;                 // staging: 0..7
    const int scol = (tid & 15) * 4;           // staging: 0..60

    for (int kv0 = 0; kv0 < NTOK; kv0 += 64) {
        __syncthreads();   // prev iteration's P/V reads complete

        // Stage K,V (tf32-convert once here)
        #pragma unroll
        for (int r = 0; r < 8; r++) {
            int row = r * 8 + srow;
            float4 kf = *(const float4*)(Kg + (size_t)(kv0 + row) * HD + scol);
            uint4 kc = make_uint4(f2tf32(kf.x), f2tf32(kf.y),
                                  f2tf32(kf.z), f2tf32(kf.w));
            *(uint4*)&Ks[row * KS_STRIDE + scol] = kc;
            float4 vf = *(const float4*)(Vg + (size_t)(kv0 + row) * HD + scol);
            uint4 vc = make_uint4(f2tf32(vf.x), f2tf32(vf.y),
                                  f2tf32(vf.z), f2tf32(vf.w));
            *(uint4*)&Vs[row * VS_STRIDE + scol] = vc;
        }
        __syncthreads();

        // ---- S = Q @ K^T ----
        float sc[8][4] = {};
        #pragma unroll
        for (int ks = 0; ks < 8; ks++) {
            #pragma unroll
            for (int n0 = 0; n0 < 8; n0++) {
                const uint32_t* krow = &Ks[(n0 * 8 + g) * KS_STRIDE + ks * 8 + t4];
                mma_tf32(sc[n0], qa[ks], krow[0], krow[4]);
            }
        }

        // ---- online softmax (two rows per thread: g and g+8) ----
        #pragma unroll
        for (int r = 0; r < 2; r++) {
            float mx = NEG_INF;
            #pragma unroll
            for (int n0 = 0; n0 < 8; n0++)
                mx = fmaxf(mx, fmaxf(sc[n0][2 * r], sc[n0][2 * r + 1]));
            mx = fmaxf(mx, __shfl_xor_sync(0xffffffffu, mx, 1));
            mx = fmaxf(mx, __shfl_xor_sync(0xffffffffu, mx, 2));
            float mnew  = fmaxf(mrow[r], mx);
            float alpha = __expf(mrow[r] - mnew);
            float rs = 0.0f;
            #pragma unroll
            for (int n0 = 0; n0 < 8; n0++) {
                sc[n0][2 * r]     = __expf(sc[n0][2 * r]     - mnew);
                sc[n0][2 * r + 1] = __expf(sc[n0][2 * r + 1] - mnew);
                rs += sc[n0][2 * r] + sc[n0][2 * r + 1];
            }
            rs += __shfl_xor_sync(0xffffffffu, rs, 1);
            rs += __shfl_xor_sync(0xffffffffu, rs, 2);
            lrow[r] = lrow[r] * alpha + rs;
            mrow[r] = mnew;
            #pragma unroll
            for (int n0 = 0; n0 < 8; n0++) {
                oc[n0][2 * r]     *= alpha;
                oc[n0][2 * r + 1] *= alpha;
            }
        }

        __syncthreads();   // all warps done reading Ks as K

        // ---- stage P (tf32) into warp-private rows of Ks ----
        uint32_t* Pw = Ks + warp * 16 * KS_STRIDE;
        #pragma unroll
        for (int n0 = 0; n0 < 8; n0++) {
            uint2 p0 = make_uint2(f2tf32(sc[n0][0]), f2tf32(sc[n0][1]));
            *(uint2*)&Pw[g * KS_STRIDE + n0 * 8 + t4 * 2] = p0;
            uint2 p1 = make_uint2(f2tf32(sc[n0][2]), f2tf32(sc[n0][3]));
            *(uint2*)&Pw[(g + 8) * KS_STRIDE + n0 * 8 + t4 * 2] = p1;
        }
        __syncwarp();

        // ---- O += P @ V ----
        #pragma unroll
        for (int ks = 0; ks < 8; ks++) {
            uint32_t pa[4];
            pa[0] = Pw[g * KS_STRIDE + ks * 8 + t4];
            pa[1] = Pw[(g + 8) * KS_STRIDE + ks * 8 + t4];
            pa[2] = Pw[g * KS_STRIDE + ks * 8 + t4 + 4];
            pa[3] = Pw[(g + 8) * KS_STRIDE + ks * 8 + t4 + 4];
            #pragma unroll
            for (int n0 = 0; n0 < 8; n0++) {
                uint32_t b0 = Vs[(ks * 8 + t4) * VS_STRIDE + n0 * 8 + g];
                uint32_t b1 = Vs[(ks * 8 + t4 + 4) * VS_STRIDE + n0 * 8 + g];
                mma_tf32(oc[n0], pa, b0, b1);
            }
        }
    }

    // Normalize (softmax row-sum and post-softmax 1/sqrt(dk)=1/8) and store
    float inv0 = 1.0f / (lrow[0] * 8.0f);
    float inv1 = 1.0f / (lrow[1] * 8.0f);
    float* __restrict__ Og = g_O + ((size_t)bh * NTOK + q0 + warp * 16) * HD;
    #pragma unroll
    for (int n0 = 0; n0 < 8; n0++) {
        float2 v0 = make_float2(oc[n0][0] * inv0, oc[n0][1] * inv0);
        *(float2*)&Og[(size_t)g * HD + n0 * 8 + t4 * 2] = v0;
        float2 v1 = make_float2(oc[n0][2] * inv1, oc[n0][3] * inv1);
        *(float2*)&Og[(size_t)(g + 8) * HD + n0 * 8 + t4 * 2] = v1;
    }
}

// ---------------------------------------------------------------------------
// Kernel 3: output projection + transpose back to [B, C, H, W] (unchanged).
// ---------------------------------------------------------------------------
__global__ __launch_bounds__(256) void out_proj_kernel(
    const float* __restrict__ Wo,
    float* __restrict__ out)
{
    __shared__ float As[16][64];
    __shared__ float Bs[16][64];
    __shared__ float Cs[64][64];

    const int b   = blockIdx.z;
    const int m0  = blockIdx.x * 64;
    const int c0  = blockIdx.y * 64;
    const int tid = threadIdx.x;
    const int tx  = tid & 15;
    const int ty  = tid >> 4;

    const int am  = tid >> 2;
    const int ak4 = (tid & 3) * 4;
    const int bk  = tid >> 4;
    const int bc4 = (tid & 15) * 4;

    float acc[4][4] = {};

    for (int k0 = 0; k0 < HIDDEN; k0 += 16) {
        const int head = k0 >> 6;
        const int kin  = (k0 & 63) + ak4;
        float4 av = *(const float4*)(g_O +
            ((size_t)(b * NH + head) * NTOK + m0 + am) * HD + kin);
        As[ak4 + 0][am] = av.x;
        As[ak4 + 1][am] = av.y;
        As[ak4 + 2][am] = av.z;
        As[ak4 + 3][am] = av.w;
        float4 bv = *(const float4*)(Wo + (size_t)(k0 + bk) * CDIM + c0 + bc4);
        *(float4*)&Bs[bk][bc4] = bv;
        __syncthreads();
        #pragma unroll
        for (int kk = 0; kk < 16; kk++) {
            float4 a  = *(float4*)&As[kk][ty * 4];
            float4 bb = *(float4*)&Bs[kk][tx * 4];
            float ar[4] = {a.x, a.y, a.z, a.w};
            float br[4] = {bb.x, bb.y, bb.z, bb.w};
            #pragma unroll
            for (int i = 0; i < 4; i++)
                #pragma unroll
                for (int j = 0; j < 4; j++)
                    acc[i][j] = fmaf(ar[i], br[j], acc[i][j]);
        }
        __syncthreads();
    }

    #pragma unroll
    for (int i = 0; i < 4; i++)
        #pragma unroll
        for (int j = 0; j < 4; j++)
            Cs[tx * 4 + j][ty * 4 + i] = acc[i][j];
    __syncthreads();

    float* __restrict__ ob = out + ((size_t)b * CDIM + c0) * NTOK + m0;
    #pragma unroll
    for (int r = 0; r < 4; r++) {
        int idx = tid + r * 256;
        int c   = idx >> 4;
        int m4  = (idx & 15) * 4;
        *(float4*)(ob + (size_t)c * NTOK + m4) = *(float4*)&Cs[c][m4];
    }
}

// ---------------------------------------------------------------------------
extern "C" void kernel_launch(void* const* d_in, const int* in_sizes, int n_in,
                              void* d_out, int out_size)
{
    const float* x  = (const float*)d_in[0];
    const float* Wq = (const float*)d_in[1];
    const float* Wk = (const float*)d_in[2];
    const float* Wv = (const float*)d_in[3];
    const float* Wo = (const float*)d_in[4];
    float* out = (float*)d_out;

    dim3 g1(NTOK / 64, 3 * HIDDEN / 64, BATCH);   // 36 x 24 x 4
    qkv_proj_kernel<<<g1, 256>>>(x, Wq, Wk, Wv);

    dim3 g2(NTOK / 64, BATCH * NH);               // 36 x 32
    flash_attn_tc_kernel<<<g2, 128>>>();

    dim3 g3(NTOK / 64, CDIM / 64, BATCH);         // 36 x 4 x 4
    out_proj_kernel<<<g3, 256>>>(Wo, out);
}

// round 6
// speedup vs baseline: 3.9759x; 1.3048x over previous
#include <cuda_runtime.h>
#include <cstdint>

// Problem constants
#define BATCH   4
#define CDIM    256
#define NTOK    2304        // 48*48
#define NH      8
#define HD      64
#define HIDDEN  (NH*HD)     // 512
#define NEG_INF (-3.0e38f)

// Scratch, TRANSPOSED layout: [B, h, d, NTOK]  (row d of length NTOK)
__device__ __align__(16) float g_Q[(size_t)BATCH*NH*HD*NTOK];
__device__ __align__(16) float g_K[(size_t)BATCH*NH*HD*NTOK];
__device__ __align__(16) float g_V[(size_t)BATCH*NH*HD*NTOK];
__device__ __align__(16) float g_O[(size_t)BATCH*NH*HD*NTOK];

// ---------------------------------------------------------------------------
// tf32 helpers
// ---------------------------------------------------------------------------
__device__ __forceinline__ uint32_t f2tf32(float x) {
    uint32_t u;
    asm("cvt.rna.tf32.f32 %0, %1;" : "=r"(u) : "f"(x));
    return u;
}

__device__ __forceinline__ uint4 cvt4(float4 f) {
    return make_uint4(f2tf32(f.x), f2tf32(f.y), f2tf32(f.z), f2tf32(f.w));
}

__device__ __forceinline__ void mma_tf32(float c[4], const uint32_t a[4],
                                         uint32_t b0, uint32_t b1) {
    asm volatile(
        "mma.sync.aligned.m16n8k8.row.col.f32.tf32.tf32.f32 "
        "{%0,%1,%2,%3}, {%4,%5,%6,%7}, {%8,%9}, {%0,%1,%2,%3};"
        : "+f"(c[0]), "+f"(c[1]), "+f"(c[2]), "+f"(c[3])
        : "r"(a[0]), "r"(a[1]), "r"(a[2]), "r"(a[3]), "r"(b0), "r"(b1));
}

// ---------------------------------------------------------------------------
// Kernel 1: QKV projection on tensor cores.
// out^T[d][tok] = sum_c W[c][h*64+d] * x[b][c][tok]
// M = 64 d-channels (per head), N = 64 tokens, K = 256.
// A = W tile staged [k][m] (natural), B = x tile staged [k][n] (natural).
// Grid: (NTOK/64, 3*NH, BATCH). Block 128 (4 warps, 16 M-rows each).
// ---------------------------------------------------------------------------
__global__ __launch_bounds__(128) void qkv_tc_kernel(
    const float* __restrict__ x,
    const float* __restrict__ Wq,
    const float* __restrict__ Wk,
    const float* __restrict__ Wv)
{
    __shared__ __align__(16) uint32_t As[32 * 72];   // W tile [k][m]
    __shared__ __align__(16) uint32_t Bs[32 * 72];   // x tile [k][n]

    const int b    = blockIdx.z;
    const int tok0 = blockIdx.x * 64;
    const int sel  = blockIdx.y >> 3;
    const int h    = blockIdx.y & 7;

    const float* __restrict__ W = (sel == 0) ? Wq : (sel == 1) ? Wk : Wv;
    float* __restrict__ Out = ((sel == 0) ? g_Q : (sel == 1) ? g_K : g_V)
                              + (size_t)(b * NH + h) * HD * NTOK;

    const int tid  = threadIdx.x;
    const int lane = tid & 31;
    const int warp = tid >> 5;
    const int g    = lane >> 2;
    const int t4   = lane & 3;

    const float* __restrict__ xb = x + (size_t)b * CDIM * NTOK;

    float oc[8][4] = {};

    for (int k0 = 0; k0 < CDIM; k0 += 32) {
        __syncthreads();
        #pragma unroll
        for (int p = 0; p < 4; p++) {
            int idx = tid + p * 128;
            int r   = idx >> 4;             // 0..31
            int c4  = (idx & 15) * 4;       // 0..60
            float4 wv = *(const float4*)(W + (size_t)(k0 + r) * HIDDEN + h * 64 + c4);
            *(uint4*)&As[r * 72 + c4] = cvt4(wv);
            float4 xv = *(const float4*)(xb + (size_t)(k0 + r) * NTOK + tok0 + c4);
            *(uint4*)&Bs[r * 72 + c4] = cvt4(xv);
        }
        __syncthreads();

        #pragma unroll
        for (int ks = 0; ks < 4; ks++) {
            uint32_t a[4];
            a[0] = As[(ks * 8 + t4) * 72 + warp * 16 + g];
            a[1] = As[(ks * 8 + t4) * 72 + warp * 16 + g + 8];
            a[2] = As[(ks * 8 + t4 + 4) * 72 + warp * 16 + g];
            a[3] = As[(ks * 8 + t4 + 4) * 72 + warp * 16 + g + 8];
            #pragma unroll
            for (int n0 = 0; n0 < 8; n0++) {
                uint32_t b0 = Bs[(ks * 8 + t4) * 72 + n0 * 8 + g];
                uint32_t b1 = Bs[(ks * 8 + t4 + 4) * 72 + n0 * 8 + g];
                mma_tf32(oc[n0], a, b0, b1);
            }
        }
    }

    // C[m=d][n=tok] -> Out[d][tok]: c0,c1 are consecutive tokens -> float2
    const int d0 = warp * 16 + g;
    #pragma unroll
    for (int n0 = 0; n0 < 8; n0++) {
        int t = tok0 + n0 * 8 + 2 * t4;
        *(float2*)&Out[(size_t)d0 * NTOK + t]       = make_float2(oc[n0][0], oc[n0][1]);
        *(float2*)&Out[(size_t)(d0 + 8) * NTOK + t] = make_float2(oc[n0][2], oc[n0][3]);
    }
}

// ---------------------------------------------------------------------------
// Kernel 2: flash attention on tensor cores (tf32 mma m16n8k8).
// Q/K/V in T-layout [d][tok]. K staged [d][j] stride 72 (reused as the P
// buffer after the S phase, as in the round-2 design); V staged [d][j]
// stride 68. All staging loads coalesced, natural stores.
// Grid: (NTOK/64, BATCH*NH). Block 128.
// ---------------------------------------------------------------------------
#define KST 72
#define VST 68

__global__ __launch_bounds__(128, 3) void flash_attn_tc_kernel()
{
    __shared__ __align__(16) uint32_t Ks[64 * KST];   // K; reused as P
    __shared__ __align__(16) uint32_t Vs[64 * VST];

    const int bh   = blockIdx.y;
    const int q0   = blockIdx.x * 64;
    const int tid  = threadIdx.x;
    const int lane = tid & 31;
    const int warp = tid >> 5;
    const int g    = lane >> 2;
    const int t4   = lane & 3;

    const float* __restrict__ Qg = g_Q + (size_t)bh * HD * NTOK;
    const float* __restrict__ Kg = g_K + (size_t)bh * HD * NTOK;
    const float* __restrict__ Vg = g_V + (size_t)bh * HD * NTOK;

    const int qg = q0 + warp * 16 + g;

    // Q A-fragments for all 8 k-steps (registers, whole kernel)
    uint32_t qa[8][4];
    #pragma unroll
    for (int ks = 0; ks < 8; ks++) {
        qa[ks][0] = f2tf32(Qg[(size_t)(ks * 8 + t4) * NTOK + qg]);
        qa[ks][1] = f2tf32(Qg[(size_t)(ks * 8 + t4) * NTOK + qg + 8]);
        qa[ks][2] = f2tf32(Qg[(size_t)(ks * 8 + t4 + 4) * NTOK + qg]);
        qa[ks][3] = f2tf32(Qg[(size_t)(ks * 8 + t4 + 4) * NTOK + qg + 8]);
    }

    float oc[8][4] = {};
    float mrow[2] = {NEG_INF, NEG_INF};
    float lrow[2] = {0.0f, 0.0f};

    for (int kv0 = 0; kv0 < NTOK; kv0 += 64) {
        __syncthreads();   // prev iteration's P/V reads complete

        // Stage K,V: row d (contiguous tokens), natural store
        #pragma unroll
        for (int p = 0; p < 8; p++) {
            int idx = tid + p * 128;
            int d   = idx >> 4;             // 0..63
            int j4  = (idx & 15) * 4;       // 0..60
            float4 kf = *(const float4*)(Kg + (size_t)d * NTOK + kv0 + j4);
            *(uint4*)&Ks[d * KST + j4] = cvt4(kf);
            float4 vf = *(const float4*)(Vg + (size_t)d * NTOK + kv0 + j4);
            *(uint4*)&Vs[d * VST + j4] = cvt4(vf);
        }
        __syncthreads();

        // ---- S = Q @ K^T : B[k=d][n=j] = KT[d][j] ----
        float sc[8][4] = {};
        #pragma unroll
        for (int ks = 0; ks < 8; ks++) {
            #pragma unroll
            for (int n0 = 0; n0 < 8; n0++) {
                uint32_t b0 = Ks[(ks * 8 + t4) * KST + n0 * 8 + g];
                uint32_t b1 = Ks[(ks * 8 + t4 + 4) * KST + n0 * 8 + g];
                mma_tf32(sc[n0], qa[ks], b0, b1);
            }
        }

        // ---- online softmax (rows g and g+8) ----
        #pragma unroll
        for (int r = 0; r < 2; r++) {
            float mx = NEG_INF;
            #pragma unroll
            for (int n0 = 0; n0 < 8; n0++)
                mx = fmaxf(mx, fmaxf(sc[n0][2 * r], sc[n0][2 * r + 1]));
            mx = fmaxf(mx, __shfl_xor_sync(0xffffffffu, mx, 1));
            mx = fmaxf(mx, __shfl_xor_sync(0xffffffffu, mx, 2));
            float mnew  = fmaxf(mrow[r], mx);
            float alpha = __expf(mrow[r] - mnew);
            float rs = 0.0f;
            #pragma unroll
            for (int n0 = 0; n0 < 8; n0++) {
                sc[n0][2 * r]     = __expf(sc[n0][2 * r]     - mnew);
                sc[n0][2 * r + 1] = __expf(sc[n0][2 * r + 1] - mnew);
                rs += sc[n0][2 * r] + sc[n0][2 * r + 1];
            }
            rs += __shfl_xor_sync(0xffffffffu, rs, 1);
            rs += __shfl_xor_sync(0xffffffffu, rs, 2);
            lrow[r] = lrow[r] * alpha + rs;
            mrow[r] = mnew;
            #pragma unroll
            for (int n0 = 0; n0 < 8; n0++) {
                oc[n0][2 * r]     *= alpha;
                oc[n0][2 * r + 1] *= alpha;
            }
        }

        __syncthreads();   // all warps done reading Ks as K

        // ---- stage P (tf32) into warp-private rows of Ks ----
        uint32_t* Pw = Ks + warp * 16 * KST;
        #pragma unroll
        for (int n0 = 0; n0 < 8; n0++) {
            *(uint2*)&Pw[g * KST + n0 * 8 + t4 * 2] =
                make_uint2(f2tf32(sc[n0][0]), f2tf32(sc[n0][1]));
            *(uint2*)&Pw[(g + 8) * KST + n0 * 8 + t4 * 2] =
                make_uint2(f2tf32(sc[n0][2]), f2tf32(sc[n0][3]));
        }
        __syncwarp();

        // ---- O += P @ V : B[k=j][n=d] = VT[d][j] ----
        #pragma unroll
        for (int ks = 0; ks < 8; ks++) {
            uint32_t pa[4];
            pa[0] = Pw[g * KST + ks * 8 + t4];
            pa[1] = Pw[(g + 8) * KST + ks * 8 + t4];
            pa[2] = Pw[g * KST + ks * 8 + t4 + 4];
            pa[3] = Pw[(g + 8) * KST + ks * 8 + t4 + 4];
            #pragma unroll
            for (int n0 = 0; n0 < 8; n0++) {
                uint32_t b0 = Vs[(n0 * 8 + g) * VST + ks * 8 + t4];
                uint32_t b1 = Vs[(n0 * 8 + g) * VST + ks * 8 + t4 + 4];
                mma_tf32(oc[n0], pa, b0, b1);
            }
        }
    }

    // Normalize (row-sum + post-softmax 1/8) and store O^T[d][qtok]
    float inv0 = 1.0f / (lrow[0] * 8.0f);
    float inv1 = 1.0f / (lrow[1] * 8.0f);
    float* __restrict__ Og = g_O + (size_t)bh * HD * NTOK;
    #pragma unroll
    for (int n0 = 0; n0 < 8; n0++) {
        int d0 = n0 * 8 + 2 * t4;
        Og[(size_t)d0 * NTOK + qg]           = oc[n0][0] * inv0;
        Og[(size_t)(d0 + 1) * NTOK + qg]     = oc[n0][1] * inv0;
        Og[(size_t)d0 * NTOK + qg + 8]       = oc[n0][2] * inv1;
        Og[(size_t)(d0 + 1) * NTOK + qg + 8] = oc[n0][3] * inv1;
    }
}

// ---------------------------------------------------------------------------
// Kernel 3: output projection on tensor cores.
// out[b][c][tok] = sum_k Wo[k][c] * O^T[k][tok]
// M = 64 channels, N = 64 tokens, K = 512.
// A = Wo natural [k][m]; B = O^T natural [k][n]; C writes straight to output.
// Grid: (NTOK/64, CDIM/64, BATCH). Block 128.
// ---------------------------------------------------------------------------
__global__ __launch_bounds__(128) void out_proj_tc_kernel(
    const float* __restrict__ Wo,
    float* __restrict__ out)
{
    __shared__ __align__(16) uint32_t As[32 * 72];   // Wo tile [k][m]
    __shared__ __align__(16) uint32_t Bs[32 * 72];   // O^T tile [k][n]

    const int b    = blockIdx.z;
    const int tok0 = blockIdx.x * 64;
    const int c0   = blockIdx.y * 64;

    const int tid  = threadIdx.x;
    const int lane = tid & 31;
    const int warp = tid >> 5;
    const int g    = lane >> 2;
    const int t4   = lane & 3;

    float oc[8][4] = {};

    for (int k0 = 0; k0 < HIDDEN; k0 += 32) {
        __syncthreads();
        #pragma unroll
        for (int p = 0; p < 4; p++) {
            int idx = tid + p * 128;
            int r   = idx >> 4;
            int c4  = (idx & 15) * 4;
            float4 wv = *(const float4*)(Wo + (size_t)(k0 + r) * CDIM + c0 + c4);
            *(uint4*)&As[r * 72 + c4] = cvt4(wv);
            // g_O global row index: b*HIDDEN + k  (since (b*NH+h)*HD + d = b*512 + k)
            float4 ov = *(const float4*)(g_O + ((size_t)b * HIDDEN + k0 + r) * NTOK + tok0 + c4);
            *(uint4*)&Bs[r * 72 + c4] = cvt4(ov);
        }
        __syncthreads();

        #pragma unroll
        for (int ks = 0; ks < 4; ks++) {
            uint32_t a[4];
            a[0] = As[(ks * 8 + t4) * 72 + warp * 16 + g];
            a[1] = As[(ks * 8 + t4) * 72 + warp * 16 + g + 8];
            a[2] = As[(ks * 8 + t4 + 4) * 72 + warp * 16 + g];
            a[3] = As[(ks * 8 + t4 + 4) * 72 + warp * 16 + g + 8];
            #pragma unroll
            for (int n0 = 0; n0 < 8; n0++) {
                uint32_t b0 = Bs[(ks * 8 + t4) * 72 + n0 * 8 + g];
                uint32_t b1 = Bs[(ks * 8 + t4 + 4) * 72 + n0 * 8 + g];
                mma_tf32(oc[n0], a, b0, b1);
            }
        }
    }

    // C[m=c][n=tok] -> out[b][c][tok]: consecutive tokens -> float2, coalesced
    const int cr = c0 + warp * 16 + g;
    #pragma unroll
    for (int n0 = 0; n0 < 8; n0++) {
        int t = tok0 + n0 * 8 + 2 * t4;
        *(float2*)&out[((size_t)b * CDIM + cr) * NTOK + t] =
            make_float2(oc[n0][0], oc[n0][1]);
        *(float2*)&out[((size_t)b * CDIM + cr + 8) * NTOK + t] =
            make_float2(oc[n0][2], oc[n0][3]);
    }
}

// ---------------------------------------------------------------------------
extern "C" void kernel_launch(void* const* d_in, const int* in_sizes, int n_in,
                              void* d_out, int out_size)
{
    const float* x  = (const float*)d_in[0];
    const float* Wq = (const float*)d_in[1];
    const float* Wk = (const float*)d_in[2];
    const float* Wv = (const float*)d_in[3];
    const float* Wo = (const float*)d_in[4];
    float* out = (float*)d_out;

    dim3 g1(NTOK / 64, 3 * NH, BATCH);        // 36 x 24 x 4
    qkv_tc_kernel<<<g1, 128>>>(x, Wq, Wk, Wv);

    dim3 g2(NTOK / 64, BATCH * NH);           // 36 x 32
    flash_attn_tc_kernel<<<g2, 128>>>();

    dim3 g3(NTOK / 64, CDIM / 64, BATCH);     // 36 x 4 x 4
    out_proj_tc_kernel<<<g3, 128>>>(Wo, out);
}